// round 15
// baseline (speedup 1.0000x reference)
#include <cuda_runtime.h>
#include <cuda_bf16.h>
#include <cstdint>
#include <cstddef>

#define M_TOK 8192
#define INF   4096
#define OUTF  4096
#define RK    16
#define BM    128
#define BN    256
#define BKE   64                  // K elems per stage row (bf16) = 128 bytes
#define KITERS (INF / BKE)        // 64
#define STAGES 3
#define A_BYTES (BM * 128)        // 16384
#define B_BYTES (BN * 128)        // 32768
#define STAGE_BYTES (A_BYTES + B_BYTES)  // 49152
#define SMEM_DYN (STAGES * STAGE_BYTES)  // 147456
#define NTHR 512

// ---- device scratch ----
__device__ float g_T[(size_t)M_TOK * RK];
__device__ __align__(1024) __nv_bfloat16 g_xb[(size_t)M_TOK * INF];
__device__ __align__(1024) __nv_bfloat16 g_wb[(size_t)OUTF * INF];

// ---------------- helpers ----------------
static __device__ __forceinline__ uint32_t smem_u32(const void* p) {
    uint32_t a;
    asm("{ .reg .u64 t; cvta.to.shared.u64 t, %1; cvt.u32.u64 %0, t; }" : "=r"(a) : "l"(p));
    return a;
}
static __device__ __forceinline__ uint32_t swz128(uint32_t off) {
    return off ^ ((off >> 3) & 0x70);
}
static __device__ __forceinline__ void cp16(uint32_t d, const void* s) {
    asm volatile("cp.async.cg.shared.global [%0], [%1], 16;" :: "r"(d), "l"(s) : "memory");
}
#define CP_COMMIT() asm volatile("cp.async.commit_group;" ::: "memory")
#define CP_WAIT(n)  asm volatile("cp.async.wait_group %0;" :: "n"(n) : "memory")

static __device__ __forceinline__ void ldsm4(uint32_t& r0, uint32_t& r1, uint32_t& r2,
                                             uint32_t& r3, uint32_t addr) {
    asm volatile("ldmatrix.sync.aligned.m8n8.x4.shared.b16 {%0,%1,%2,%3}, [%4];"
                 : "=r"(r0), "=r"(r1), "=r"(r2), "=r"(r3) : "r"(addr));
}
static __device__ __forceinline__ void hmma(float& d0, float& d1, float& d2, float& d3,
                                            uint32_t a0, uint32_t a1, uint32_t a2, uint32_t a3,
                                            uint32_t b0, uint32_t b1) {
    asm volatile(
        "mma.sync.aligned.m16n8k16.row.col.f32.bf16.bf16.f32 "
        "{%0,%1,%2,%3}, {%4,%5,%6,%7}, {%8,%9}, {%0,%1,%2,%3};"
        : "+f"(d0), "+f"(d1), "+f"(d2), "+f"(d3)
        : "r"(a0), "r"(a1), "r"(a2), "r"(a3), "r"(b0), "r"(b1));
}

// int32-promotion detection: int32-encoded int8 values all lie in [-300, 300].
static __device__ __forceinline__ int detect_fmt(const void* p, unsigned mask) {
    const int* pi = (const int*)p;
    int cnt = 0;
#pragma unroll
    for (int j = 0; j < 8; j++) {
        int v = pi[((unsigned)(j * 1048573 + 97) * 2654435761u) & mask];
        cnt += (v >= -300 && v <= 300);
    }
    return cnt >= 6;
}

// ---- fused prep: blocks [0, M_TOK) pack x + compute T; rest pack w ----
__global__ void __launch_bounds__(128) prep_all(const void* __restrict__ xp,
                                                const void* __restrict__ wp,
                                                const float* __restrict__ la) {
    __shared__ int s_fmt;
    __shared__ float red[4][RK];
    const int t = threadIdx.x;

    if (blockIdx.x < M_TOK) {
        const int m = blockIdx.x;
        if (t == 0) s_fmt = detect_fmt(xp, 8388607u);
        __syncthreads();
        const int fmt = s_fmt;

        __nv_bfloat16* __restrict__ dst = g_xb + (size_t)m * INF;
        float acc[RK];
#pragma unroll
        for (int r = 0; r < RK; r++) acc[r] = 0.f;

#pragma unroll
        for (int j = 0; j < 8; j++) {
            const int k0 = j * 512 + t * 4;
            float f0, f1, f2, f3;
            if (fmt) {
                int4 v = ((const int4*)xp)[((size_t)m * INF + k0) >> 2];
                f0 = (float)v.x; f1 = (float)v.y; f2 = (float)v.z; f3 = (float)v.w;
            } else {
                char4 c = ((const char4*)xp)[((size_t)m * INF + k0) >> 2];
                f0 = (float)c.x; f1 = (float)c.y; f2 = (float)c.z; f3 = (float)c.w;
            }
            ((__nv_bfloat162*)dst)[k0 >> 1]       = __floats2bfloat162_rn(f0, f1);
            ((__nv_bfloat162*)dst)[(k0 >> 1) + 1] = __floats2bfloat162_rn(f2, f3);
#pragma unroll
            for (int r = 0; r < RK; r++) {
                float4 a = *(const float4*)(la + (size_t)r * INF + k0);
                acc[r] = fmaf(f0, a.x, acc[r]);
                acc[r] = fmaf(f1, a.y, acc[r]);
                acc[r] = fmaf(f2, a.z, acc[r]);
                acc[r] = fmaf(f3, a.w, acc[r]);
            }
        }
#pragma unroll
        for (int off = 16; off >= 1; off >>= 1)
#pragma unroll
            for (int r = 0; r < RK; r++)
                acc[r] += __shfl_xor_sync(0xffffffffu, acc[r], off);
        const int wid = t >> 5, lane = t & 31;
        if (lane == 0)
#pragma unroll
            for (int r = 0; r < RK; r++) red[wid][r] = acc[r];
        __syncthreads();
        if (t < RK)
            g_T[(size_t)m * RK + t] = red[0][t] + red[1][t] + red[2][t] + red[3][t];
    } else {
        const int n = blockIdx.x - M_TOK;
        if (t == 0) s_fmt = detect_fmt(wp, 4194303u);
        __syncthreads();
        const int fmt = s_fmt;
        __nv_bfloat16* __restrict__ dst = g_wb + (size_t)n * INF;
#pragma unroll
        for (int j = 0; j < 8; j++) {
            const int k0 = j * 512 + t * 4;
            float f0, f1, f2, f3;
            if (fmt) {
                int4 v = ((const int4*)wp)[((size_t)n * INF + k0) >> 2];
                f0 = (float)v.x; f1 = (float)v.y; f2 = (float)v.z; f3 = (float)v.w;
            } else {
                char4 c = ((const char4*)wp)[((size_t)n * INF + k0) >> 2];
                f0 = (float)c.x; f1 = (float)c.y; f2 = (float)c.z; f3 = (float)c.w;
            }
            ((__nv_bfloat162*)dst)[k0 >> 1]       = __floats2bfloat162_rn(f0, f1);
            ((__nv_bfloat162*)dst)[(k0 >> 1) + 1] = __floats2bfloat162_rn(f2, f3);
        }
    }
}

// ------------- main: bf16 HMMA, CTA 128x256, 16 warps, warp 32x64 --------
static __device__ __forceinline__ void load_stage(uint32_t base, int m0, int n0, int kt, int t) {
    const __nv_bfloat16* __restrict__ gA = g_xb + (size_t)m0 * INF + kt * BKE;
    const __nv_bfloat16* __restrict__ gB = g_wb + (size_t)n0 * INF + kt * BKE;
#pragma unroll
    for (int i = 0; i < 2; i++) {                 // A: 1024 chunks of 16B
        int c = t + NTHR * i;
        int row = c >> 3, j = c & 7;
        cp16(base + swz128((uint32_t)(row * 128 + j * 16)),
             (const void*)(gA + (size_t)row * INF + j * 8));
    }
#pragma unroll
    for (int i = 0; i < 4; i++) {                 // B: 2048 chunks of 16B
        int c = t + NTHR * i;
        int row = c >> 3, j = c & 7;
        cp16(base + (uint32_t)A_BYTES + swz128((uint32_t)(row * 128 + j * 16)),
             (const void*)(gB + (size_t)row * INF + j * 8));
    }
}

static __device__ __forceinline__ void load_frags(uint32_t sA, uint32_t sB, int ks,
                                                  int m_warp, int n_warp, int lane,
                                                  uint32_t a[2][4], uint32_t b[8][2]) {
#pragma unroll
    for (int am = 0; am < 2; am++) {
        int row = m_warp + am * 16 + (((lane >> 3) & 1) * 8) + (lane & 7);
        int col = ks * 32 + ((lane >> 4) * 16);
        ldsm4(a[am][0], a[am][1], a[am][2], a[am][3],
              sA + swz128((uint32_t)(row * 128 + col)));
    }
#pragma unroll
    for (int p = 0; p < 4; p++) {
        int row = n_warp + p * 16 + (((lane >> 4) & 1) * 8) + (lane & 7);
        int col = ks * 32 + (((lane >> 3) & 1) * 16);
        ldsm4(b[2 * p][0], b[2 * p][1], b[2 * p + 1][0], b[2 * p + 1][1],
              sB + swz128((uint32_t)(row * 128 + col)));
    }
}

__global__ void __launch_bounds__(NTHR, 1)
gemm_kernel(float* __restrict__ out,
            const float* __restrict__ xsc, const float* __restrict__ wsc,
            const float* __restrict__ bias, const float* __restrict__ lora_b,
            const unsigned int* __restrict__ fgp) {
    extern __shared__ __align__(1024) unsigned char dsm[];

    const int t = threadIdx.x;
    const int wid = t >> 5, lane = t & 31;
    const int g = lane >> 2, tig = lane & 3;
    const int wm = wid & 3, wn = wid >> 2;        // 4 warps in M, 4 in N
    const int m_warp = wm * 32, n_warp = wn * 64;
    const int n0 = blockIdx.x * BN, m0 = blockIdx.y * BM;

    const uint32_t smem0 = smem_u32(dsm);

    float c[2][8][4];                             // 2 m16 atoms x 8 n8 octets
#pragma unroll
    for (int am = 0; am < 2; am++)
#pragma unroll
        for (int na = 0; na < 8; na++)
#pragma unroll
            for (int f = 0; f < 4; f++) c[am][na][f] = 0.f;

#pragma unroll
    for (int s = 0; s < 2; s++) {
        load_stage(smem0 + s * STAGE_BYTES, m0, n0, s, t);
        CP_COMMIT();
    }

    int kslot = 0;
    for (int kt = 0; kt < KITERS; kt++) {
        CP_WAIT(1);
        __syncthreads();   // all warps done reading slot (kt+2)%3 (consumed at kt-1)

        // early distance-2 prefetch into the just-vacated slot
        {
            int ws = kslot + 2; if (ws >= STAGES) ws -= STAGES;
            if (kt + 2 < KITERS)
                load_stage(smem0 + (uint32_t)ws * STAGE_BYTES, m0, n0, kt + 2, t);
        }
        CP_COMMIT();

        const uint32_t sA = smem0 + (uint32_t)kslot * STAGE_BYTES;
        const uint32_t sB = sA + (uint32_t)A_BYTES;

        // fragment double-buffer: ldsm for ks+1 issues before hmma of ks,
        // so crossbar (LDSM) and tensor (HMMA) pipes overlap.
        uint32_t a[2][2][4], b[2][8][2];
        load_frags(sA, sB, 0, m_warp, n_warp, lane, a[0], b[0]);
#pragma unroll
        for (int ks = 0; ks < 4; ks++) {
            const int cur = ks & 1, nxt = cur ^ 1;
            if (ks < 3)
                load_frags(sA, sB, ks + 1, m_warp, n_warp, lane, a[nxt], b[nxt]);
#pragma unroll
            for (int am = 0; am < 2; am++)
#pragma unroll
                for (int na = 0; na < 8; na++)
                    hmma(c[am][na][0], c[am][na][1], c[am][na][2], c[am][na][3],
                         a[cur][am][0], a[cur][am][1], a[cur][am][2], a[cur][am][3],
                         b[cur][na][0], b[cur][na][1]);
        }

        if (++kslot == STAGES) kslot = 0;
    }

    CP_WAIT(0);
    __syncthreads();

    // ---- epilogue ----
    float* Ts   = (float*)dsm;                    // [128][16]
    float* Bs   = (float*)(dsm + 8192);           // [256][16]
    float* s_xs = (float*)(dsm + 24576);          // [128]
    float* s_ws = (float*)(dsm + 25088);          // [256]
    float* s_bs = (float*)(dsm + 26112);          // [256]

    {
        const float4* tg = (const float4*)(g_T + (size_t)m0 * RK);
        const float4* bg = (const float4*)(lora_b + (size_t)n0 * RK);
        float4* ts4 = (float4*)Ts;
        float4* bs4 = (float4*)Bs;
        if (t < 512) ts4[t] = tg[t];
#pragma unroll
        for (int i = 0; i < 2; i++) bs4[t + NTHR * i] = bg[t + NTHR * i];
        if (t < 128) s_xs[t] = xsc[m0 + t];
        if (t < 256) {
            s_ws[t] = wsc[n0 + t];
            s_bs[t] = bias[n0 + t];
        }
    }
    __syncthreads();

    const bool fg = fgp ? (fgp[0] != 0u) : true;

#pragma unroll
    for (int am = 0; am < 2; am++) {
#pragma unroll
        for (int h = 0; h < 2; h++) {
            const int rowT = m_warp + am * 16 + h * 8 + g;
            const float xsv = s_xs[rowT];
            const float4* tp = (const float4*)(Ts + rowT * 16);
            const float4 t0 = tp[0], t1 = tp[1], t2 = tp[2], t3 = tp[3];
            float* __restrict__ orow = out + (size_t)(m0 + rowT) * OUTF + n0;

#pragma unroll
            for (int na = 0; na < 8; na++) {
                const int colb = n_warp + na * 8 + 2 * tig;
                float v2[2];
#pragma unroll
                for (int cp = 0; cp < 2; cp++) {
                    const int col = colb + cp;
                    const float4* bp = (const float4*)(Bs + col * 16);
                    const float4 b0 = bp[0], b1 = bp[1], b2 = bp[2], b3 = bp[3];
                    float lora = t0.x * b0.x;
                    lora = fmaf(t0.y, b0.y, lora); lora = fmaf(t0.z, b0.z, lora);
                    lora = fmaf(t0.w, b0.w, lora); lora = fmaf(t1.x, b1.x, lora);
                    lora = fmaf(t1.y, b1.y, lora); lora = fmaf(t1.z, b1.z, lora);
                    lora = fmaf(t1.w, b1.w, lora); lora = fmaf(t2.x, b2.x, lora);
                    lora = fmaf(t2.y, b2.y, lora); lora = fmaf(t2.z, b2.z, lora);
                    lora = fmaf(t2.w, b2.w, lora); lora = fmaf(t3.x, b3.x, lora);
                    lora = fmaf(t3.y, b3.y, lora); lora = fmaf(t3.z, b3.z, lora);
                    lora = fmaf(t3.w, b3.w, lora);

                    const float fa = c[am][na][(h << 1) | cp];
                    float v = fmaf(xsv, fmaf(fa, s_ws[col], lora), s_bs[col]);
                    if (fg) {
                        const float u = v * v * v;
                        const float arg = -1.5957691216f * fmaf(0.044715f, u, v);
                        v = __fdividef(v, 1.0f + __expf(arg));
                    }
                    v2[cp] = v;
                }
                *(float2*)(orow + colb) = make_float2(v2[0], v2[1]);
            }
        }
    }
}

extern "C" void kernel_launch(void* const* d_in, const int* in_sizes, int n_in,
                              void* d_out, int out_size) {
    const void*  x    = nullptr;
    const void*  wgt  = nullptr;
    const float* bias = nullptr;
    const float* xsc  = nullptr;
    const float* wsc  = nullptr;
    const float* la   = nullptr;
    const float* lb   = nullptr;
    const unsigned int* fg = nullptr;
    int seenB = 0, seenL = 0;
    for (int i = 0; i < n_in; i++) {
        const long long s = in_sizes[i];
        if (s == 33554432 || s == 134217728) x = d_in[i];
        else if (s == 16777216 || s == 67108864) wgt = d_in[i];
        else if (s == 8192 || s == 32768) xsc = (const float*)d_in[i];
        else if (s == 65536 || s == 262144) {
            if (seenL++ == 0) la = (const float*)d_in[i];
            else              lb = (const float*)d_in[i];
        } else if (s == 4096 || s == 16384) {
            if (seenB++ == 0) bias = (const float*)d_in[i];
            else              wsc  = (const float*)d_in[i];
        } else if (s == 1 || s == 4) {
            fg = (const unsigned int*)d_in[i];
        }
    }
    if (!x || !wgt || !bias || !xsc || !wsc || !la || !lb) {
        x    = d_in[0];
        wgt  = d_in[1];
        bias = (const float*)d_in[2];
        xsc  = (const float*)d_in[3];
        wsc  = (const float*)d_in[4];
        la   = (const float*)d_in[5];
        lb   = (const float*)d_in[6];
        fg   = (n_in >= 8) ? (const unsigned int*)d_in[7] : nullptr;
    }
    float* out = (float*)d_out;

    cudaFuncSetAttribute(gemm_kernel, cudaFuncAttributeMaxDynamicSharedMemorySize, SMEM_DYN);

    prep_all<<<M_TOK + OUTF, 128>>>(x, wgt, la);
    gemm_kernel<<<dim3(OUTF / BN, M_TOK / BM), NTHR, SMEM_DYN>>>(
        out, xsc, wsc, bias, lb, fg);
}

// round 16
// speedup vs baseline: 1.0217x; 1.0217x over previous
#include <cuda_runtime.h>
#include <cuda_bf16.h>
#include <cstdint>
#include <cstddef>

#define M_TOK 8192
#define INF   4096
#define OUTF  4096
#define RK    16
#define BM    128
#define BN    256
#define BKE   64                  // K elems per stage row (bf16) = 128 bytes
#define KITERS (INF / BKE)        // 64
#define STAGES 4
#define A_BYTES (BM * 128)        // 16384
#define B_BYTES (BN * 128)        // 32768
#define STAGE_BYTES (A_BYTES + B_BYTES)  // 49152
#define SMEM_DYN (STAGES * STAGE_BYTES)  // 196608
#define NTHR 512

// ---- device scratch ----
__device__ float g_T[(size_t)M_TOK * RK];
__device__ __align__(1024) __nv_bfloat16 g_xb[(size_t)M_TOK * INF];
__device__ __align__(1024) __nv_bfloat16 g_wb[(size_t)OUTF * INF];

// ---------------- helpers ----------------
static __device__ __forceinline__ uint32_t smem_u32(const void* p) {
    uint32_t a;
    asm("{ .reg .u64 t; cvta.to.shared.u64 t, %1; cvt.u32.u64 %0, t; }" : "=r"(a) : "l"(p));
    return a;
}
static __device__ __forceinline__ uint32_t swz128(uint32_t off) {
    return off ^ ((off >> 3) & 0x70);
}
static __device__ __forceinline__ void cp16(uint32_t d, const void* s) {
    asm volatile("cp.async.cg.shared.global [%0], [%1], 16;" :: "r"(d), "l"(s) : "memory");
}

// ---- mbarrier pipeline primitives (no CTA-wide barrier in mainloop) ----
#define MBAR_INIT(a, c) \
    asm volatile("mbarrier.init.shared.b64 [%0], %1;" :: "r"(a), "r"((uint32_t)(c)) : "memory")
static __device__ __forceinline__ void mbar_arrive(uint32_t a) {
    asm volatile("mbarrier.arrive.shared.b64 _, [%0];" :: "r"(a) : "memory");
}
static __device__ __forceinline__ void cpasync_arrive_noinc(uint32_t a) {
    asm volatile("cp.async.mbarrier.arrive.noinc.shared.b64 [%0];" :: "r"(a) : "memory");
}
static __device__ __forceinline__ void mbar_wait(uint32_t a, uint32_t parity) {
    asm volatile(
        "{\n\t.reg .pred P;\n\t"
        "W_%=:\n\t"
        "mbarrier.try_wait.parity.acquire.cta.shared::cta.b64 P, [%0], %1, 0x989680;\n\t"
        "@!P bra W_%=;\n\t}"
        :: "r"(a), "r"(parity) : "memory");
}

static __device__ __forceinline__ void ldsm4(uint32_t& r0, uint32_t& r1, uint32_t& r2,
                                             uint32_t& r3, uint32_t addr) {
    asm volatile("ldmatrix.sync.aligned.m8n8.x4.shared.b16 {%0,%1,%2,%3}, [%4];"
                 : "=r"(r0), "=r"(r1), "=r"(r2), "=r"(r3) : "r"(addr));
}
static __device__ __forceinline__ void hmma(float& d0, float& d1, float& d2, float& d3,
                                            uint32_t a0, uint32_t a1, uint32_t a2, uint32_t a3,
                                            uint32_t b0, uint32_t b1) {
    asm volatile(
        "mma.sync.aligned.m16n8k16.row.col.f32.bf16.bf16.f32 "
        "{%0,%1,%2,%3}, {%4,%5,%6,%7}, {%8,%9}, {%0,%1,%2,%3};"
        : "+f"(d0), "+f"(d1), "+f"(d2), "+f"(d3)
        : "r"(a0), "r"(a1), "r"(a2), "r"(a3), "r"(b0), "r"(b1));
}

// int32-promotion detection: int32-encoded int8 values all lie in [-300, 300].
static __device__ __forceinline__ int detect_fmt(const void* p, unsigned mask) {
    const int* pi = (const int*)p;
    int cnt = 0;
#pragma unroll
    for (int j = 0; j < 8; j++) {
        int v = pi[((unsigned)(j * 1048573 + 97) * 2654435761u) & mask];
        cnt += (v >= -300 && v <= 300);
    }
    return cnt >= 6;
}

// ---- fused prep: blocks [0, M_TOK) pack x + compute T; rest pack w ----
__global__ void __launch_bounds__(128) prep_all(const void* __restrict__ xp,
                                                const void* __restrict__ wp,
                                                const float* __restrict__ la) {
    __shared__ int s_fmt;
    __shared__ float red[4][RK];
    const int t = threadIdx.x;

    if (blockIdx.x < M_TOK) {
        const int m = blockIdx.x;
        if (t == 0) s_fmt = detect_fmt(xp, 8388607u);
        __syncthreads();
        const int fmt = s_fmt;

        __nv_bfloat16* __restrict__ dst = g_xb + (size_t)m * INF;
        float acc[RK];
#pragma unroll
        for (int r = 0; r < RK; r++) acc[r] = 0.f;

#pragma unroll
        for (int j = 0; j < 8; j++) {
            const int k0 = j * 512 + t * 4;
            float f0, f1, f2, f3;
            if (fmt) {
                int4 v = ((const int4*)xp)[((size_t)m * INF + k0) >> 2];
                f0 = (float)v.x; f1 = (float)v.y; f2 = (float)v.z; f3 = (float)v.w;
            } else {
                char4 c = ((const char4*)xp)[((size_t)m * INF + k0) >> 2];
                f0 = (float)c.x; f1 = (float)c.y; f2 = (float)c.z; f3 = (float)c.w;
            }
            ((__nv_bfloat162*)dst)[k0 >> 1]       = __floats2bfloat162_rn(f0, f1);
            ((__nv_bfloat162*)dst)[(k0 >> 1) + 1] = __floats2bfloat162_rn(f2, f3);
#pragma unroll
            for (int r = 0; r < RK; r++) {
                float4 a = *(const float4*)(la + (size_t)r * INF + k0);
                acc[r] = fmaf(f0, a.x, acc[r]);
                acc[r] = fmaf(f1, a.y, acc[r]);
                acc[r] = fmaf(f2, a.z, acc[r]);
                acc[r] = fmaf(f3, a.w, acc[r]);
            }
        }
#pragma unroll
        for (int off = 16; off >= 1; off >>= 1)
#pragma unroll
            for (int r = 0; r < RK; r++)
                acc[r] += __shfl_xor_sync(0xffffffffu, acc[r], off);
        const int wid = t >> 5, lane = t & 31;
        if (lane == 0)
#pragma unroll
            for (int r = 0; r < RK; r++) red[wid][r] = acc[r];
        __syncthreads();
        if (t < RK)
            g_T[(size_t)m * RK + t] = red[0][t] + red[1][t] + red[2][t] + red[3][t];
    } else {
        const int n = blockIdx.x - M_TOK;
        if (t == 0) s_fmt = detect_fmt(wp, 4194303u);
        __syncthreads();
        const int fmt = s_fmt;
        __nv_bfloat16* __restrict__ dst = g_wb + (size_t)n * INF;
#pragma unroll
        for (int j = 0; j < 8; j++) {
            const int k0 = j * 512 + t * 4;
            float f0, f1, f2, f3;
            if (fmt) {
                int4 v = ((const int4*)wp)[((size_t)n * INF + k0) >> 2];
                f0 = (float)v.x; f1 = (float)v.y; f2 = (float)v.z; f3 = (float)v.w;
            } else {
                char4 c = ((const char4*)wp)[((size_t)n * INF + k0) >> 2];
                f0 = (float)c.x; f1 = (float)c.y; f2 = (float)c.z; f3 = (float)c.w;
            }
            ((__nv_bfloat162*)dst)[k0 >> 1]       = __floats2bfloat162_rn(f0, f1);
            ((__nv_bfloat162*)dst)[(k0 >> 1) + 1] = __floats2bfloat162_rn(f2, f3);
        }
    }
}

// ------------- main: bf16 HMMA, CTA 128x256, 16 warps, warp 32x64 --------
static __device__ __forceinline__ void load_stage(uint32_t base, int m0, int n0, int kt, int t) {
    const __nv_bfloat16* __restrict__ gA = g_xb + (size_t)m0 * INF + kt * BKE;
    const __nv_bfloat16* __restrict__ gB = g_wb + (size_t)n0 * INF + kt * BKE;
#pragma unroll
    for (int i = 0; i < 2; i++) {                 // A: 1024 chunks of 16B
        int c = t + NTHR * i;
        int row = c >> 3, j = c & 7;
        cp16(base + swz128((uint32_t)(row * 128 + j * 16)),
             (const void*)(gA + (size_t)row * INF + j * 8));
    }
#pragma unroll
    for (int i = 0; i < 4; i++) {                 // B: 2048 chunks of 16B
        int c = t + NTHR * i;
        int row = c >> 3, j = c & 7;
        cp16(base + (uint32_t)A_BYTES + swz128((uint32_t)(row * 128 + j * 16)),
             (const void*)(gB + (size_t)row * INF + j * 8));
    }
}

__global__ void __launch_bounds__(NTHR, 1)
gemm_kernel(float* __restrict__ out,
            const float* __restrict__ xsc, const float* __restrict__ wsc,
            const float* __restrict__ bias, const float* __restrict__ lora_b,
            const unsigned int* __restrict__ fgp) {
    extern __shared__ __align__(1024) unsigned char dsm[];
    __shared__ __align__(8) unsigned long long s_mb[2 * STAGES];  // full[0..3], empty[0..3]

    const int t = threadIdx.x;
    const int wid = t >> 5, lane = t & 31;
    const int g = lane >> 2, tig = lane & 3;
    const int wm = wid & 3, wn = wid >> 2;        // 4 warps in M, 4 in N
    const int m_warp = wm * 32, n_warp = wn * 64;
    const int n0 = blockIdx.x * BN, m0 = blockIdx.y * BM;

    const uint32_t smem0 = smem_u32(dsm);
    const uint32_t mb0 = smem_u32(s_mb);
#define FULL_MB(s)  (mb0 + (uint32_t)(s) * 8u)
#define EMPTY_MB(s) (mb0 + (uint32_t)(STAGES + (s)) * 8u)

    if (t == 0) {
#pragma unroll
        for (int s = 0; s < STAGES; s++) {
            MBAR_INIT(FULL_MB(s), NTHR);
            MBAR_INIT(EMPTY_MB(s), NTHR);
        }
    }
    __syncthreads();

    float c[2][8][4];                             // 2 m16 atoms x 8 n8 octets
#pragma unroll
    for (int am = 0; am < 2; am++)
#pragma unroll
        for (int na = 0; na < 8; na++)
#pragma unroll
            for (int f = 0; f < 4; f++) c[am][na][f] = 0.f;

    // prologue: fill slots 0..2 (no empty-wait needed; never read yet)
#pragma unroll
    for (int s = 0; s < 3; s++) {
        load_stage(smem0 + s * STAGE_BYTES, m0, n0, s, t);
        cpasync_arrive_noinc(FULL_MB(s));
    }

    unsigned fph = 0, eph = 0;                    // per-slot parity bits
    for (int kt = 0; kt < KITERS; kt++) {
        const int s = kt & 3;

        // produce stage kt+3 into slot (kt+3)&3 (the slot read at kt-1)
        if (kt + 3 < KITERS) {
            const int ws = (kt + 3) & 3;
            if (kt >= 1) {
                mbar_wait(EMPTY_MB(ws), (eph >> ws) & 1u);
                eph ^= 1u << ws;
            }
            load_stage(smem0 + (uint32_t)ws * STAGE_BYTES, m0, n0, kt + 3, t);
            cpasync_arrive_noinc(FULL_MB(ws));
        }

        // consume slot s (fast-path no-op once warm -> warps stay de-phased)
        mbar_wait(FULL_MB(s), (fph >> s) & 1u);
        fph ^= 1u << s;

        const uint32_t sA = smem0 + (uint32_t)s * STAGE_BYTES;
        const uint32_t sB = sA + (uint32_t)A_BYTES;

#pragma unroll
        for (int ks = 0; ks < 4; ks++) {
            uint32_t a[2][4];
#pragma unroll
            for (int am = 0; am < 2; am++) {
                int row = m_warp + am * 16 + (((lane >> 3) & 1) * 8) + (lane & 7);
                int col = ks * 32 + ((lane >> 4) * 16);
                ldsm4(a[am][0], a[am][1], a[am][2], a[am][3],
                      sA + swz128((uint32_t)(row * 128 + col)));
            }
            uint32_t b[8][2];
#pragma unroll
            for (int p = 0; p < 4; p++) {
                int row = n_warp + p * 16 + (((lane >> 4) & 1) * 8) + (lane & 7);
                int col = ks * 32 + (((lane >> 3) & 1) * 16);
                ldsm4(b[2 * p][0], b[2 * p][1], b[2 * p + 1][0], b[2 * p + 1][1],
                      sB + swz128((uint32_t)(row * 128 + col)));
            }
#pragma unroll
            for (int am = 0; am < 2; am++)
#pragma unroll
                for (int na = 0; na < 8; na++)
                    hmma(c[am][na][0], c[am][na][1], c[am][na][2], c[am][na][3],
                         a[am][0], a[am][1], a[am][2], a[am][3],
                         b[na][0], b[na][1]);
        }

        mbar_arrive(EMPTY_MB(s));                 // done reading slot s
    }

    __syncthreads();                              // re-join warps before smem reuse

    // ---- epilogue ----
    float* Ts   = (float*)dsm;                    // [128][16]
    float* Bs   = (float*)(dsm + 8192);           // [256][16]
    float* s_xs = (float*)(dsm + 24576);          // [128]
    float* s_ws = (float*)(dsm + 25088);          // [256]
    float* s_bs = (float*)(dsm + 26112);          // [256]

    {
        const float4* tg = (const float4*)(g_T + (size_t)m0 * RK);
        const float4* bg = (const float4*)(lora_b + (size_t)n0 * RK);
        float4* ts4 = (float4*)Ts;
        float4* bs4 = (float4*)Bs;
        if (t < 512) ts4[t] = tg[t];
#pragma unroll
        for (int i = 0; i < 2; i++) bs4[t + NTHR * i] = bg[t + NTHR * i];
        if (t < 128) s_xs[t] = xsc[m0 + t];
        if (t < 256) {
            s_ws[t] = wsc[n0 + t];
            s_bs[t] = bias[n0 + t];
        }
    }
    __syncthreads();

    const bool fg = fgp ? (fgp[0] != 0u) : true;

#pragma unroll
    for (int am = 0; am < 2; am++) {
#pragma unroll
        for (int h = 0; h < 2; h++) {
            const int rowT = m_warp + am * 16 + h * 8 + g;
            const float xsv = s_xs[rowT];
            const float4* tp = (const float4*)(Ts + rowT * 16);
            const float4 t0 = tp[0], t1 = tp[1], t2 = tp[2], t3 = tp[3];
            float* __restrict__ orow = out + (size_t)(m0 + rowT) * OUTF + n0;

#pragma unroll
            for (int na = 0; na < 8; na++) {
                const int colb = n_warp + na * 8 + 2 * tig;
                float v2[2];
#pragma unroll
                for (int cp = 0; cp < 2; cp++) {
                    const int col = colb + cp;
                    const float4* bp = (const float4*)(Bs + col * 16);
                    const float4 b0 = bp[0], b1 = bp[1], b2 = bp[2], b3 = bp[3];
                    float lora = t0.x * b0.x;
                    lora = fmaf(t0.y, b0.y, lora); lora = fmaf(t0.z, b0.z, lora);
                    lora = fmaf(t0.w, b0.w, lora); lora = fmaf(t1.x, b1.x, lora);
                    lora = fmaf(t1.y, b1.y, lora); lora = fmaf(t1.z, b1.z, lora);
                    lora = fmaf(t1.w, b1.w, lora); lora = fmaf(t2.x, b2.x, lora);
                    lora = fmaf(t2.y, b2.y, lora); lora = fmaf(t2.z, b2.z, lora);
                    lora = fmaf(t2.w, b2.w, lora); lora = fmaf(t3.x, b3.x, lora);
                    lora = fmaf(t3.y, b3.y, lora); lora = fmaf(t3.z, b3.z, lora);
                    lora = fmaf(t3.w, b3.w, lora);

                    const float fa = c[am][na][(h << 1) | cp];
                    float v = fmaf(xsv, fmaf(fa, s_ws[col], lora), s_bs[col]);
                    if (fg) {
                        const float u = v * v * v;
                        const float arg = -1.5957691216f * fmaf(0.044715f, u, v);
                        v = __fdividef(v, 1.0f + __expf(arg));
                    }
                    v2[cp] = v;
                }
                *(float2*)(orow + colb) = make_float2(v2[0], v2[1]);
            }
        }
    }
}

extern "C" void kernel_launch(void* const* d_in, const int* in_sizes, int n_in,
                              void* d_out, int out_size) {
    const void*  x    = nullptr;
    const void*  wgt  = nullptr;
    const float* bias = nullptr;
    const float* xsc  = nullptr;
    const float* wsc  = nullptr;
    const float* la   = nullptr;
    const float* lb   = nullptr;
    const unsigned int* fg = nullptr;
    int seenB = 0, seenL = 0;
    for (int i = 0; i < n_in; i++) {
        const long long s = in_sizes[i];
        if (s == 33554432 || s == 134217728) x = d_in[i];
        else if (s == 16777216 || s == 67108864) wgt = d_in[i];
        else if (s == 8192 || s == 32768) xsc = (const float*)d_in[i];
        else if (s == 65536 || s == 262144) {
            if (seenL++ == 0) la = (const float*)d_in[i];
            else              lb = (const float*)d_in[i];
        } else if (s == 4096 || s == 16384) {
            if (seenB++ == 0) bias = (const float*)d_in[i];
            else              wsc  = (const float*)d_in[i];
        } else if (s == 1 || s == 4) {
            fg = (const unsigned int*)d_in[i];
        }
    }
    if (!x || !wgt || !bias || !xsc || !wsc || !la || !lb) {
        x    = d_in[0];
        wgt  = d_in[1];
        bias = (const float*)d_in[2];
        xsc  = (const float*)d_in[3];
        wsc  = (const float*)d_in[4];
        la   = (const float*)d_in[5];
        lb   = (const float*)d_in[6];
        fg   = (n_in >= 8) ? (const unsigned int*)d_in[7] : nullptr;
    }
    float* out = (float*)d_out;

    cudaFuncSetAttribute(gemm_kernel, cudaFuncAttributeMaxDynamicSharedMemorySize, SMEM_DYN);

    prep_all<<<M_TOK + OUTF, 128>>>(x, wgt, la);
    gemm_kernel<<<dim3(OUTF / BN, M_TOK / BM), NTHR, SMEM_DYN>>>(
        out, xsc, wsc, bias, lb, fg);
}

// round 17
// speedup vs baseline: 1.0989x; 1.0756x over previous
#include <cuda_runtime.h>
#include <cuda_bf16.h>
#include <cstdint>
#include <cstddef>

#define M_TOK 8192
#define INF   4096
#define OUTF  4096
#define RK    16
#define BM    128
#define BN    256
#define BKE   64                  // K elems per stage row (bf16) = 128 bytes
#define KITERS (INF / BKE)        // 64
#define STAGES 3
#define A_BYTES (BM * 128)        // 16384
#define B_BYTES (BN * 128)        // 32768
#define STAGE_BYTES (A_BYTES + B_BYTES)  // 49152
#define SMEM_DYN (STAGES * STAGE_BYTES)  // 147456

// ---- device scratch ----
__device__ float g_T[(size_t)M_TOK * RK];
__device__ __align__(1024) __nv_bfloat16 g_xb[(size_t)M_TOK * INF];
__device__ __align__(1024) __nv_bfloat16 g_wb[(size_t)OUTF * INF];

// ---------------- helpers ----------------
static __device__ __forceinline__ uint32_t smem_u32(const void* p) {
    uint32_t a;
    asm("{ .reg .u64 t; cvta.to.shared.u64 t, %1; cvt.u32.u64 %0, t; }" : "=r"(a) : "l"(p));
    return a;
}
static __device__ __forceinline__ uint32_t swz128(uint32_t off) {
    return off ^ ((off >> 3) & 0x70);
}
static __device__ __forceinline__ void cp16(uint32_t d, const void* s) {
    asm volatile("cp.async.cg.shared.global [%0], [%1], 16;" :: "r"(d), "l"(s) : "memory");
}
#define CP_COMMIT() asm volatile("cp.async.commit_group;" ::: "memory")
#define CP_WAIT(n)  asm volatile("cp.async.wait_group %0;" :: "n"(n) : "memory")

static __device__ __forceinline__ void ldsm4(uint32_t& r0, uint32_t& r1, uint32_t& r2,
                                             uint32_t& r3, uint32_t addr) {
    asm volatile("ldmatrix.sync.aligned.m8n8.x4.shared.b16 {%0,%1,%2,%3}, [%4];"
                 : "=r"(r0), "=r"(r1), "=r"(r2), "=r"(r3) : "r"(addr));
}
static __device__ __forceinline__ void hmma(float& d0, float& d1, float& d2, float& d3,
                                            uint32_t a0, uint32_t a1, uint32_t a2, uint32_t a3,
                                            uint32_t b0, uint32_t b1) {
    asm volatile(
        "mma.sync.aligned.m16n8k16.row.col.f32.bf16.bf16.f32 "
        "{%0,%1,%2,%3}, {%4,%5,%6,%7}, {%8,%9}, {%0,%1,%2,%3};"
        : "+f"(d0), "+f"(d1), "+f"(d2), "+f"(d3)
        : "r"(a0), "r"(a1), "r"(a2), "r"(a3), "r"(b0), "r"(b1));
}

// int32-promotion detection: int32-encoded int8 values all lie in [-300, 300].
static __device__ __forceinline__ int detect_fmt(const void* p, unsigned mask) {
    const int* pi = (const int*)p;
    int cnt = 0;
#pragma unroll
    for (int j = 0; j < 8; j++) {
        int v = pi[((unsigned)(j * 1048573 + 97) * 2654435761u) & mask];
        cnt += (v >= -300 && v <= 300);
    }
    return cnt >= 6;
}

// ---- fused prep: blocks [0, M_TOK) pack x + compute T; rest pack w ----
// Restructured for MLP: phase 1 loads the whole row into registers (8
// independent loads), converts + stores; phase 2 streams la with 16
// accumulators (latency hidden). Same per-thread arithmetic order as before.
__global__ void __launch_bounds__(128) prep_all(const void* __restrict__ xp,
                                                const void* __restrict__ wp,
                                                const float* __restrict__ la) {
    __shared__ int s_fmt;
    __shared__ float red[4][RK];
    const int t = threadIdx.x;

    if (blockIdx.x < M_TOK) {
        const int m = blockIdx.x;
        if (t == 0) s_fmt = detect_fmt(xp, 8388607u);
        __syncthreads();
        const int fmt = s_fmt;

        __nv_bfloat16* __restrict__ dst = g_xb + (size_t)m * INF;

        // ---- phase 1: load full row (MLP=8), convert, store bf16 ----
        float f[32];
        if (fmt) {
            int4 v[8];
#pragma unroll
            for (int j = 0; j < 8; j++)
                v[j] = ((const int4*)xp)[((size_t)m * INF + j * 512 + t * 4) >> 2];
#pragma unroll
            for (int j = 0; j < 8; j++) {
                f[4 * j + 0] = (float)v[j].x; f[4 * j + 1] = (float)v[j].y;
                f[4 * j + 2] = (float)v[j].z; f[4 * j + 3] = (float)v[j].w;
            }
        } else {
            char4 c[8];
#pragma unroll
            for (int j = 0; j < 8; j++)
                c[j] = ((const char4*)xp)[((size_t)m * INF + j * 512 + t * 4) >> 2];
#pragma unroll
            for (int j = 0; j < 8; j++) {
                f[4 * j + 0] = (float)c[j].x; f[4 * j + 1] = (float)c[j].y;
                f[4 * j + 2] = (float)c[j].z; f[4 * j + 3] = (float)c[j].w;
            }
        }
#pragma unroll
        for (int j = 0; j < 8; j++) {
            const int k0 = j * 512 + t * 4;
            ((__nv_bfloat162*)dst)[k0 >> 1]       = __floats2bfloat162_rn(f[4 * j], f[4 * j + 1]);
            ((__nv_bfloat162*)dst)[(k0 >> 1) + 1] = __floats2bfloat162_rn(f[4 * j + 2], f[4 * j + 3]);
        }

        // ---- phase 2: T = x @ la^T, 16 accumulators, streaming la loads ----
        float acc[RK];
#pragma unroll
        for (int r = 0; r < RK; r++) acc[r] = 0.f;
#pragma unroll
        for (int j = 0; j < 8; j++) {
            const int k0 = j * 512 + t * 4;
#pragma unroll
            for (int r = 0; r < RK; r++) {
                float4 a = *(const float4*)(la + (size_t)r * INF + k0);
                acc[r] = fmaf(f[4 * j + 0], a.x, acc[r]);
                acc[r] = fmaf(f[4 * j + 1], a.y, acc[r]);
                acc[r] = fmaf(f[4 * j + 2], a.z, acc[r]);
                acc[r] = fmaf(f[4 * j + 3], a.w, acc[r]);
            }
        }
#pragma unroll
        for (int off = 16; off >= 1; off >>= 1)
#pragma unroll
            for (int r = 0; r < RK; r++)
                acc[r] += __shfl_xor_sync(0xffffffffu, acc[r], off);
        const int wid = t >> 5, lane = t & 31;
        if (lane == 0)
#pragma unroll
            for (int r = 0; r < RK; r++) red[wid][r] = acc[r];
        __syncthreads();
        if (t < RK)
            g_T[(size_t)m * RK + t] = red[0][t] + red[1][t] + red[2][t] + red[3][t];
    } else {
        const int n = blockIdx.x - M_TOK;
        if (t == 0) s_fmt = detect_fmt(wp, 4194303u);
        __syncthreads();
        const int fmt = s_fmt;
        __nv_bfloat16* __restrict__ dst = g_wb + (size_t)n * INF;
        if (fmt) {
            int4 v[8];
#pragma unroll
            for (int j = 0; j < 8; j++)
                v[j] = ((const int4*)wp)[((size_t)n * INF + j * 512 + t * 4) >> 2];
#pragma unroll
            for (int j = 0; j < 8; j++) {
                const int k0 = j * 512 + t * 4;
                ((__nv_bfloat162*)dst)[k0 >> 1] =
                    __floats2bfloat162_rn((float)v[j].x, (float)v[j].y);
                ((__nv_bfloat162*)dst)[(k0 >> 1) + 1] =
                    __floats2bfloat162_rn((float)v[j].z, (float)v[j].w);
            }
        } else {
            char4 c[8];
#pragma unroll
            for (int j = 0; j < 8; j++)
                c[j] = ((const char4*)wp)[((size_t)n * INF + j * 512 + t * 4) >> 2];
#pragma unroll
            for (int j = 0; j < 8; j++) {
                const int k0 = j * 512 + t * 4;
                ((__nv_bfloat162*)dst)[k0 >> 1] =
                    __floats2bfloat162_rn((float)c[j].x, (float)c[j].y);
                ((__nv_bfloat162*)dst)[(k0 >> 1) + 1] =
                    __floats2bfloat162_rn((float)c[j].z, (float)c[j].w);
            }
        }
    }
}

// ---------------- main: bf16 HMMA GEMM, CTA 128x256, warp 64x64 ----------
// (R10 configuration verbatim — the best measured gemm, ~737 us)
static __device__ __forceinline__ void load_stage(uint32_t base, int m0, int n0, int kt, int t) {
    const __nv_bfloat16* __restrict__ gA = g_xb + (size_t)m0 * INF + kt * BKE;
    const __nv_bfloat16* __restrict__ gB = g_wb + (size_t)n0 * INF + kt * BKE;
#pragma unroll
    for (int i = 0; i < 4; i++) {                 // A: 1024 chunks of 16B
        int c = t + 256 * i;
        int row = c >> 3, j = c & 7;
        cp16(base + swz128((uint32_t)(row * 128 + j * 16)),
             (const void*)(gA + (size_t)row * INF + j * 8));
    }
#pragma unroll
    for (int i = 0; i < 8; i++) {                 // B: 2048 chunks of 16B
        int c = t + 256 * i;
        int row = c >> 3, j = c & 7;
        cp16(base + (uint32_t)A_BYTES + swz128((uint32_t)(row * 128 + j * 16)),
             (const void*)(gB + (size_t)row * INF + j * 8));
    }
}

__global__ void __launch_bounds__(256, 1)
gemm_kernel(float* __restrict__ out,
            const float* __restrict__ xsc, const float* __restrict__ wsc,
            const float* __restrict__ bias, const float* __restrict__ lora_b,
            const unsigned int* __restrict__ fgp) {
    extern __shared__ __align__(1024) unsigned char dsm[];

    const int t = threadIdx.x;
    const int wid = t >> 5, lane = t & 31;
    const int g = lane >> 2, tig = lane & 3;
    const int wm = wid & 1, wn = wid >> 1;        // 2 warps in M, 4 in N
    const int m_warp = wm * 64, n_warp = wn * 64;
    const int n0 = blockIdx.x * BN, m0 = blockIdx.y * BM;

    const uint32_t smem0 = smem_u32(dsm);

    float c[4][8][4];                             // 4 m16 atoms x 8 n8 octets
#pragma unroll
    for (int am = 0; am < 4; am++)
#pragma unroll
        for (int na = 0; na < 8; na++)
#pragma unroll
            for (int f = 0; f < 4; f++) c[am][na][f] = 0.f;

#pragma unroll
    for (int s = 0; s < 2; s++) {
        load_stage(smem0 + s * STAGE_BYTES, m0, n0, s, t);
        CP_COMMIT();
    }

    int kslot = 0;
    for (int kt = 0; kt < KITERS; kt++) {
        CP_WAIT(1);
        __syncthreads();

        const uint32_t sA = smem0 + (uint32_t)kslot * STAGE_BYTES;
        const uint32_t sB = sA + (uint32_t)A_BYTES;

#pragma unroll
        for (int ks = 0; ks < 4; ks++) {
            uint32_t a[4][4];
#pragma unroll
            for (int am = 0; am < 4; am++) {
                int row = m_warp + am * 16 + (((lane >> 3) & 1) * 8) + (lane & 7);
                int col = ks * 32 + ((lane >> 4) * 16);
                ldsm4(a[am][0], a[am][1], a[am][2], a[am][3],
                      sA + swz128((uint32_t)(row * 128 + col)));
            }
            uint32_t b[8][2];
#pragma unroll
            for (int p = 0; p < 4; p++) {
                int row = n_warp + p * 16 + (((lane >> 4) & 1) * 8) + (lane & 7);
                int col = ks * 32 + (((lane >> 3) & 1) * 16);
                ldsm4(b[2 * p][0], b[2 * p][1], b[2 * p + 1][0], b[2 * p + 1][1],
                      sB + swz128((uint32_t)(row * 128 + col)));
            }
#pragma unroll
            for (int am = 0; am < 4; am++)
#pragma unroll
                for (int na = 0; na < 8; na++)
                    hmma(c[am][na][0], c[am][na][1], c[am][na][2], c[am][na][3],
                         a[am][0], a[am][1], a[am][2], a[am][3],
                         b[na][0], b[na][1]);
        }

        if (kt + 2 < KITERS) {
            int ws = kslot + 2; if (ws >= STAGES) ws -= STAGES;
            load_stage(smem0 + (uint32_t)ws * STAGE_BYTES, m0, n0, kt + 2, t);
        }
        CP_COMMIT();
        if (++kslot == STAGES) kslot = 0;
    }

    CP_WAIT(0);
    __syncthreads();

    // ---- epilogue ----
    float* Ts   = (float*)dsm;                    // [128][16]
    float* Bs   = (float*)(dsm + 8192);           // [256][16]
    float* s_xs = (float*)(dsm + 24576);          // [128]
    float* s_ws = (float*)(dsm + 25088);          // [256]
    float* s_bs = (float*)(dsm + 26112);          // [256]

    {
        const float4* tg = (const float4*)(g_T + (size_t)m0 * RK);
        const float4* bg = (const float4*)(lora_b + (size_t)n0 * RK);
        float4* ts4 = (float4*)Ts;
        float4* bs4 = (float4*)Bs;
#pragma unroll
        for (int i = 0; i < 2; i++) ts4[t + 256 * i] = tg[t + 256 * i];
#pragma unroll
        for (int i = 0; i < 4; i++) bs4[t + 256 * i] = bg[t + 256 * i];
        if (t < 128) s_xs[t] = xsc[m0 + t];
        s_ws[t] = wsc[n0 + t];
        s_bs[t] = bias[n0 + t];
    }
    __syncthreads();

    const bool fg = fgp ? (fgp[0] != 0u) : true;

#pragma unroll
    for (int am = 0; am < 4; am++) {
#pragma unroll
        for (int h = 0; h < 2; h++) {
            const int rowT = m_warp + am * 16 + h * 8 + g;
            const float xsv = s_xs[rowT];
            const float4* tp = (const float4*)(Ts + rowT * 16);
            const float4 t0 = tp[0], t1 = tp[1], t2 = tp[2], t3 = tp[3];
            float* __restrict__ orow = out + (size_t)(m0 + rowT) * OUTF + n0;

#pragma unroll
            for (int na = 0; na < 8; na++) {
                const int colb = n_warp + na * 8 + 2 * tig;
                float v2[2];
#pragma unroll
                for (int cp = 0; cp < 2; cp++) {
                    const int col = colb + cp;
                    const float4* bp = (const float4*)(Bs + col * 16);
                    const float4 b0 = bp[0], b1 = bp[1], b2 = bp[2], b3 = bp[3];
                    float lora = t0.x * b0.x;
                    lora = fmaf(t0.y, b0.y, lora); lora = fmaf(t0.z, b0.z, lora);
                    lora = fmaf(t0.w, b0.w, lora); lora = fmaf(t1.x, b1.x, lora);
                    lora = fmaf(t1.y, b1.y, lora); lora = fmaf(t1.z, b1.z, lora);
                    lora = fmaf(t1.w, b1.w, lora); lora = fmaf(t2.x, b2.x, lora);
                    lora = fmaf(t2.y, b2.y, lora); lora = fmaf(t2.z, b2.z, lora);
                    lora = fmaf(t2.w, b2.w, lora); lora = fmaf(t3.x, b3.x, lora);
                    lora = fmaf(t3.y, b3.y, lora); lora = fmaf(t3.z, b3.z, lora);
                    lora = fmaf(t3.w, b3.w, lora);

                    const float fa = c[am][na][(h << 1) | cp];
                    float v = fmaf(xsv, fmaf(fa, s_ws[col], lora), s_bs[col]);
                    if (fg) {
                        const float u = v * v * v;
                        const float arg = -1.5957691216f * fmaf(0.044715f, u, v);
                        v = __fdividef(v, 1.0f + __expf(arg));
                    }
                    v2[cp] = v;
                }
                *(float2*)(orow + colb) = make_float2(v2[0], v2[1]);
            }
        }
    }
}

extern "C" void kernel_launch(void* const* d_in, const int* in_sizes, int n_in,
                              void* d_out, int out_size) {
    const void*  x    = nullptr;
    const void*  wgt  = nullptr;
    const float* bias = nullptr;
    const float* xsc  = nullptr;
    const float* wsc  = nullptr;
    const float* la   = nullptr;
    const float* lb   = nullptr;
    const unsigned int* fg = nullptr;
    int seenB = 0, seenL = 0;
    for (int i = 0; i < n_in; i++) {
        const long long s = in_sizes[i];
        if (s == 33554432 || s == 134217728) x = d_in[i];
        else if (s == 16777216 || s == 67108864) wgt = d_in[i];
        else if (s == 8192 || s == 32768) xsc = (const float*)d_in[i];
        else if (s == 65536 || s == 262144) {
            if (seenL++ == 0) la = (const float*)d_in[i];
            else              lb = (const float*)d_in[i];
        } else if (s == 4096 || s == 16384) {
            if (seenB++ == 0) bias = (const float*)d_in[i];
            else              wsc  = (const float*)d_in[i];
        } else if (s == 1 || s == 4) {
            fg = (const unsigned int*)d_in[i];
        }
    }
    if (!x || !wgt || !bias || !xsc || !wsc || !la || !lb) {
        x    = d_in[0];
        wgt  = d_in[1];
        bias = (const float*)d_in[2];
        xsc  = (const float*)d_in[3];
        wsc  = (const float*)d_in[4];
        la   = (const float*)d_in[5];
        lb   = (const float*)d_in[6];
        fg   = (n_in >= 8) ? (const unsigned int*)d_in[7] : nullptr;
    }
    float* out = (float*)d_out;

    cudaFuncSetAttribute(gemm_kernel, cudaFuncAttributeMaxDynamicSharedMemorySize, SMEM_DYN);

    prep_all<<<M_TOK + OUTF, 128>>>(x, wgt, la);
    gemm_kernel<<<dim3(OUTF / BN, M_TOK / BM), 256, SMEM_DYN>>>(
        out, xsc, wsc, bias, lb, fg);
}